// round 13
// baseline (speedup 1.0000x reference)
#include <cuda_runtime.h>
#include <cuda_bf16.h>
#include <math.h>

// ---------------- problem constants ----------------
#define BATCH 512
#define TIN   512
#define CCH   6
#define HID   12
#define NLAY  120
#define T1    508
#define T2    504
#define RD    16
#define NTH3  256
#define NOUT  (BATCH*NLAY*HID)

typedef unsigned long long u64;
typedef unsigned int u32;

// ---------------- smem layout for k_lstm3 ----------------
// A_hi/A_lo: [512][40] bf16 (80 B rows; cols 0-11 x, 12-23 h, 24 bias, 25-39 pad)
// G: [48][513] f32 transposed gates
// W_hi/W_lo: [48][32] bf16
#define SA_HI 0
#define SA_LO 40960
#define SG    81920
#define SW_HI 180416
#define SW_LO 183488
#define LSTM3_SMEM 186560

// ---------------- device scratch ----------------
__device__ double g_s1[CCH], g_q1[CCH], g_s2[CCH], g_q2[CCH];
__device__ float  g_bn1[2*CCH];
__device__ float  g_bn2[2*CCH];
__device__ float  g_buf1[BATCH*CCH*T1];
__device__ float  g_buf2[BATCH*CCH*T2];
__device__ float  g_seq [BATCH*T2*HID];              // [b][t][h]
__device__ float  g_hid [BATCH*NLAY*HID];
__device__ float  g_ring[(size_t)NLAY*RD*BATCH*HID]; // pipeline ring
__device__ int    g_flag[NLAY];
__device__ int    g_done[NLAY+1];

// ---------------- helpers ----------------
__device__ __forceinline__ float tanh_t(float x) {
    float y;
    asm("tanh.approx.f32 %0, %1;" : "=f"(y) : "f"(x));
    return y;
}
__device__ __forceinline__ float sigm_pre(float hx) {   // acc pre-scaled by 0.5
    return fmaf(0.5f, tanh_t(hx), 0.5f);
}
// pack two f32 -> bf16x2 (lower = lo_val, upper = hi_val)
__device__ __forceinline__ u32 pkbf2(float lo_val, float hi_val) {
    u32 r;
    asm("cvt.rn.bf16x2.f32 %0, %1, %2;" : "=r"(r) : "f"(hi_val), "f"(lo_val));
    return r;
}
__device__ __forceinline__ float f2bf_f(float x) {
    __nv_bfloat16 b = __float2bfloat16(x);
    return __bfloat162float(b);
}
__device__ __forceinline__ void mma16816(float& c0, float& c1, float& c2, float& c3,
                                         const u32* a, const u32* b) {
    asm volatile(
        "mma.sync.aligned.m16n8k16.row.col.f32.bf16.bf16.f32 "
        "{%0,%1,%2,%3}, {%4,%5,%6,%7}, {%8,%9}, {%0,%1,%2,%3};"
        : "+f"(c0), "+f"(c1), "+f"(c2), "+f"(c3)
        : "r"(a[0]), "r"(a[1]), "r"(a[2]), "r"(a[3]), "r"(b[0]), "r"(b[1]));
}

// ---------------- K0: zero accumulators + pipeline flags ----------------
__global__ void k_zero() {
    int t = threadIdx.x;
    if (t < CCH) { g_s1[t] = 0.0; g_q1[t] = 0.0; g_s2[t] = 0.0; g_q2[t] = 0.0; }
    for (int q = t; q < NLAY; q += blockDim.x) g_flag[q] = 0;
    for (int q = t; q < NLAY + 1; q += blockDim.x) g_done[q] = 0;
}

// ---------------- K1: conv1 + BN1 stats ----------------
__global__ void k_conv1(const float* __restrict__ x,
                        const float* __restrict__ w,
                        const float* __restrict__ bias) {
    int b = blockIdx.x;
    int tid = threadIdx.x;
    __shared__ float xs[CCH * TIN];
    __shared__ float ws[CCH * CCH * 5];
    __shared__ float bs[CCH];
    for (int i = tid; i < CCH * TIN; i += blockDim.x) xs[i] = x[b * CCH * TIN + i];
    if (tid < CCH * CCH * 5) ws[tid] = w[tid];
    if (tid < CCH) bs[tid] = bias[tid];
    __syncthreads();

    for (int c = 0; c < CCH; c++) {
        float s = 0.f, q = 0.f;
        for (int t = tid; t < T1; t += blockDim.x) {
            float a = bs[c];
            #pragma unroll
            for (int ci = 0; ci < CCH; ci++) {
                const float* xp = xs + ci * TIN + t;
                const float* wp = ws + (c * CCH + ci) * 5;
                #pragma unroll
                for (int k = 0; k < 5; k++) a = fmaf(xp[k], wp[k], a);
            }
            g_buf1[(b * CCH + c) * T1 + t] = a;
            s += a; q += a * a;
        }
        #pragma unroll
        for (int off = 16; off > 0; off >>= 1) {
            s += __shfl_down_sync(0xffffffffu, s, off);
            q += __shfl_down_sync(0xffffffffu, q, off);
        }
        if ((tid & 31) == 0) {
            atomicAdd(&g_s1[c], (double)s);
            atomicAdd(&g_q1[c], (double)q);
        }
    }
}

// ---------------- K2/K4: finalize BN ----------------
__global__ void k_bnfin(const float* __restrict__ gam,
                        const float* __restrict__ bet, int which) {
    int c = threadIdx.x;
    if (c < CCH) {
        double* S = which ? g_s2 : g_s1;
        double* Q = which ? g_q2 : g_q1;
        float* out = which ? g_bn2 : g_bn1;
        double n = which ? ((double)BATCH * T2) : ((double)BATCH * T1);
        double m = S[c] / n;
        double v = Q[c] / n - m * m;
        float sc = gam[c] * rsqrtf((float)v + 1e-5f);
        out[c] = sc;
        out[CCH + c] = bet[c] - (float)m * sc;
    }
}

// ---------------- K3: BN1+relu -> conv2 + BN2 stats ----------------
__global__ void k_conv2(const float* __restrict__ w,
                        const float* __restrict__ bias) {
    int b = blockIdx.x;
    int tid = threadIdx.x;
    __shared__ float xs[CCH * T1];
    __shared__ float ws[CCH * CCH * 5];
    __shared__ float bs[CCH];
    for (int i = tid; i < CCH * T1; i += blockDim.x) {
        int ci = i / T1;
        float v = g_buf1[b * CCH * T1 + i];
        xs[i] = fmaxf(fmaf(v, g_bn1[ci], g_bn1[CCH + ci]), 0.f);
    }
    if (tid < CCH * CCH * 5) ws[tid] = w[tid];
    if (tid < CCH) bs[tid] = bias[tid];
    __syncthreads();

    for (int c = 0; c < CCH; c++) {
        float s = 0.f, q = 0.f;
        for (int t = tid; t < T2; t += blockDim.x) {
            float a = bs[c];
            #pragma unroll
            for (int ci = 0; ci < CCH; ci++) {
                const float* xp = xs + ci * T1 + t;
                const float* wp = ws + (c * CCH + ci) * 5;
                #pragma unroll
                for (int k = 0; k < 5; k++) a = fmaf(xp[k], wp[k], a);
            }
            g_buf2[(b * CCH + c) * T2 + t] = a;
            s += a; q += a * a;
        }
        #pragma unroll
        for (int off = 16; off > 0; off >>= 1) {
            s += __shfl_down_sync(0xffffffffu, s, off);
            q += __shfl_down_sync(0xffffffffu, q, off);
        }
        if ((tid & 31) == 0) {
            atomicAdd(&g_s2[c], (double)s);
            atomicAdd(&g_q2[c], (double)q);
        }
    }
}

// ---------------- K5: BN2+relu -> attn -> seq [b][t][h] ----------------
__global__ void k_attn(const float* __restrict__ aw,
                       const float* __restrict__ ab) {
    int b = blockIdx.x;
    int tid = threadIdx.x;
    __shared__ float xs[CCH * T2];
    __shared__ float ws[HID * CCH];
    __shared__ float bs[HID];
    for (int i = tid; i < CCH * T2; i += blockDim.x) {
        int ci = i / T2;
        float v = g_buf2[b * CCH * T2 + i];
        xs[i] = fmaxf(fmaf(v, g_bn2[ci], g_bn2[CCH + ci]), 0.f);
    }
    if (tid < HID * CCH) ws[tid] = aw[tid];
    if (tid < HID) bs[tid] = ab[tid];
    __syncthreads();

    for (int idx = tid; idx < T2 * HID; idx += blockDim.x) {
        int t = idx / HID, h = idx % HID;
        float a = bs[h];
        #pragma unroll
        for (int c = 0; c < CCH; c++) a = fmaf(xs[c * T2 + t], ws[h * CCH + c], a);
        g_seq[(size_t)b * T2 * HID + idx] = fmaxf(a, 0.f);
    }
}

// ---------------- K6: layer-per-SM LSTM pipeline via mma.sync (bf16 hi/lo) ----------------
// One block per layer (120 blocks, 1/SM by smem). 256 threads; each thread owns
// batches {tid, tid+256}. Per tick: gates = [x|h|1] @ W^T via m16n8k16 bf16 MMA
// with double-bf16 split (hi*hi + hi*lo + lo*hi, f32 acc). Sigmoid rows of W
// pre-scaled by 0.5; bias folded in as K-column 24 (A[.][24]=1). Layers pipeline
// through g_ring (depth 16, release/acquire flags + consumer credits).
__global__ void __launch_bounds__(NTH3, 1)
k_lstm3(const float* __restrict__ Wih, const float* __restrict__ Whh,
        const float* __restrict__ bih, const float* __restrict__ bhh) {
    extern __shared__ __align__(16) char sm[];
    int l = blockIdx.x;
    int tid = threadIdx.x;
    int lane = tid & 31, wp = tid >> 5;
    int kp = lane & 3, grp = lane >> 2;

    // zero A_hi + A_lo
    for (int q = tid; q < SG / 4; q += NTH3) ((u32*)sm)[q] = 0;
    // build W hi/lo tiles [48 rows n][32 k]; sigmoid rows (n<24 or n>=36) * 0.5
    for (int idx = tid; idx < 48 * 32; idx += NTH3) {
        int n = idx >> 5, k = idx & 31;
        float w = 0.f;
        if (k < 12)       w = Wih[((size_t)l * 48 + n) * 12 + k];
        else if (k < 24)  w = Whh[((size_t)l * 48 + n) * 12 + (k - 12)];
        else if (k == 24) w = bih[l * 48 + n] + bhh[l * 48 + n];
        if (!(n >= 24 && n < 36)) w *= 0.5f;
        __nv_bfloat16 hb = __float2bfloat16(w);
        __nv_bfloat16 lb = __float2bfloat16(w - __bfloat162float(hb));
        *(__nv_bfloat16*)(sm + SW_HI + n * 64 + k * 2) = hb;
        *(__nv_bfloat16*)(sm + SW_LO + n * 64 + k * 2) = lb;
    }
    __syncthreads();
    // bias column k=24 in A_hi = 1.0 (A_lo stays 0)
    for (int b = tid; b < BATCH; b += NTH3)
        *(unsigned short*)(sm + SA_HI + b * 80 + 48) = 0x3F80;

    // preload B fragments (W^T col-major view): per (nt, kt): 2 regs
    u32 Bh[6][2][2], Bl[6][2][2];
    #pragma unroll
    for (int nt = 0; nt < 6; nt++)
        #pragma unroll
        for (int kt = 0; kt < 2; kt++) {
            u32 off = (u32)(nt * 8 + grp) * 64 + kt * 32 + kp * 4;
            Bh[nt][kt][0] = *(u32*)(sm + SW_HI + off);
            Bh[nt][kt][1] = *(u32*)(sm + SW_HI + off + 16);
            Bl[nt][kt][0] = *(u32*)(sm + SW_LO + off);
            Bl[nt][kt][1] = *(u32*)(sm + SW_LO + off + 16);
        }

    float cst[2][HID], hv[2][HID];
    #pragma unroll
    for (int s = 0; s < 2; s++)
        #pragma unroll
        for (int u = 0; u < HID; u++) { cst[s][u] = 0.f; hv[s][u] = 0.f; }

    float* G = (float*)(sm + SG);
    __syncthreads();

    for (int t = 0; t < T2; t++) {
        // acquire upstream data + downstream ring credit
        if (tid == 0) {
            if (l > 0)
                while (((volatile int*)g_flag)[l - 1] < t + 1) __nanosleep(64);
            if (l < NLAY - 1 && t >= RD)
                while (((volatile int*)g_done)[l + 1] < t - RD + 1) __nanosleep(64);
            __threadfence();
        }
        __syncthreads();

        // stage A rows for both owned batches: x (cols 0-11), h (cols 12-23)
        #pragma unroll
        for (int s = 0; s < 2; s++) {
            int b = tid + s * 256;
            float xv[HID];
            if (l == 0) {
                const float4* p = (const float4*)(g_seq + ((size_t)b * T2 + t) * HID);
                float4 A = p[0], B = p[1], C = p[2];
                xv[0]=A.x; xv[1]=A.y; xv[2]=A.z; xv[3]=A.w;
                xv[4]=B.x; xv[5]=B.y; xv[6]=B.z; xv[7]=B.w;
                xv[8]=C.x; xv[9]=C.y; xv[10]=C.z; xv[11]=C.w;
            } else {
                const float4* p = (const float4*)(g_ring +
                    (((size_t)(l - 1) * RD + (t & (RD - 1))) * BATCH + b) * HID);
                float4 A = __ldcg(p), B = __ldcg(p + 1), C = __ldcg(p + 2);
                xv[0]=A.x; xv[1]=A.y; xv[2]=A.z; xv[3]=A.w;
                xv[4]=B.x; xv[5]=B.y; xv[6]=B.z; xv[7]=B.w;
                xv[8]=C.x; xv[9]=C.y; xv[10]=C.z; xv[11]=C.w;
            }
            char* rh = sm + SA_HI + (size_t)b * 80;
            char* rl = sm + SA_LO + (size_t)b * 80;
            #pragma unroll
            for (int q = 0; q < 6; q++) {
                float v0 = xv[2 * q], v1 = xv[2 * q + 1];
                *(u32*)(rh + 4 * q) = pkbf2(v0, v1);
                *(u32*)(rl + 4 * q) = pkbf2(v0 - f2bf_f(v0), v1 - f2bf_f(v1));
            }
            #pragma unroll
            for (int q = 0; q < 6; q++) {
                float v0 = hv[s][2 * q], v1 = hv[s][2 * q + 1];
                *(u32*)(rh + 24 + 4 * q) = pkbf2(v0, v1);
                *(u32*)(rl + 24 + 4 * q) = pkbf2(v0 - f2bf_f(v0), v1 - f2bf_f(v1));
            }
        }
        __syncthreads();

        // upstream ring slot consumed -> publish credit
        if (tid == 0 && l > 0) {
            __threadfence();
            ((volatile int*)g_done)[l] = t + 1;
        }

        // MMA: each warp 64 batches (4 m-tiles) x 48 gates (6 n-tiles)
        #pragma unroll
        for (int mt = 0; mt < 4; mt++) {
            int r0 = wp * 64 + mt * 16 + grp, r1 = r0 + 8;
            u32 ah[2][4], al[2][4];
            #pragma unroll
            for (int kt = 0; kt < 2; kt++) {
                u32 o0 = (u32)r0 * 80 + kt * 32 + kp * 4;
                u32 o1 = (u32)r1 * 80 + kt * 32 + kp * 4;
                ah[kt][0] = *(u32*)(sm + SA_HI + o0);
                ah[kt][1] = *(u32*)(sm + SA_HI + o1);
                ah[kt][2] = *(u32*)(sm + SA_HI + o0 + 16);
                ah[kt][3] = *(u32*)(sm + SA_HI + o1 + 16);
                al[kt][0] = *(u32*)(sm + SA_LO + o0);
                al[kt][1] = *(u32*)(sm + SA_LO + o1);
                al[kt][2] = *(u32*)(sm + SA_LO + o0 + 16);
                al[kt][3] = *(u32*)(sm + SA_LO + o1 + 16);
            }
            #pragma unroll
            for (int nt = 0; nt < 6; nt++) {
                float c0 = 0.f, c1 = 0.f, c2 = 0.f, c3 = 0.f;
                mma16816(c0, c1, c2, c3, ah[0], Bh[nt][0]);
                mma16816(c0, c1, c2, c3, ah[1], Bh[nt][1]);
                mma16816(c0, c1, c2, c3, ah[0], Bl[nt][0]);
                mma16816(c0, c1, c2, c3, ah[1], Bl[nt][1]);
                mma16816(c0, c1, c2, c3, al[0], Bh[nt][0]);
                mma16816(c0, c1, c2, c3, al[1], Bh[nt][1]);
                int n0 = nt * 8 + kp * 2;
                G[(size_t)n0 * 513 + r0]       = c0;
                G[(size_t)(n0 + 1) * 513 + r0] = c1;
                G[(size_t)n0 * 513 + r1]       = c2;
                G[(size_t)(n0 + 1) * 513 + r1] = c3;
            }
        }
        __syncthreads();

        // activations + state update + outputs
        #pragma unroll
        for (int s = 0; s < 2; s++) {
            int b = tid + s * 256;
            #pragma unroll
            for (int u = 0; u < HID; u++) {
                float gi = sigm_pre(G[(size_t)u * 513 + b]);
                float gf = sigm_pre(G[(size_t)(12 + u) * 513 + b]);
                float gg = tanh_t (G[(size_t)(24 + u) * 513 + b]);
                float go = sigm_pre(G[(size_t)(36 + u) * 513 + b]);
                cst[s][u] = fmaf(gf, cst[s][u], gi * gg);
                hv[s][u] = go * tanh_t(cst[s][u]);
            }
            if (l < NLAY - 1) {
                float4* p = (float4*)(g_ring +
                    (((size_t)l * RD + (t & (RD - 1))) * BATCH + b) * HID);
                __stcg(p,     make_float4(hv[s][0], hv[s][1], hv[s][2],  hv[s][3]));
                __stcg(p + 1, make_float4(hv[s][4], hv[s][5], hv[s][6],  hv[s][7]));
                __stcg(p + 2, make_float4(hv[s][8], hv[s][9], hv[s][10], hv[s][11]));
            }
            if (t == T2 - 1) {
                float4* p = (float4*)(g_hid + ((size_t)b * NLAY + l) * HID);
                p[0] = make_float4(hv[s][0], hv[s][1], hv[s][2],  hv[s][3]);
                p[1] = make_float4(hv[s][4], hv[s][5], hv[s][6],  hv[s][7]);
                p[2] = make_float4(hv[s][8], hv[s][9], hv[s][10], hv[s][11]);
            }
        }
        __syncthreads();
        // release this tick to downstream
        if (tid == 0 && l < NLAY - 1) {
            __threadfence();
            ((volatile int*)g_flag)[l] = t + 1;
        }
    }
}

// ---------------- K7: MLP head -> (z, out, mu, log_var) ----------------
__global__ void k_head(const float* __restrict__ eps,
                       const float* __restrict__ l1w, const float* __restrict__ l1b,
                       const float* __restrict__ l2w, const float* __restrict__ l2b,
                       const float* __restrict__ muw, const float* __restrict__ mub,
                       const float* __restrict__ lvw, const float* __restrict__ lvb,
                       float* __restrict__ out) {
    __shared__ float W1[144], W2[144], WM[144], WV[144];
    __shared__ float B1[12], B2[12], BM[12], BV[12];
    int tid = threadIdx.x;
    for (int q = tid; q < 144; q += blockDim.x) {
        W1[q] = l1w[q]; W2[q] = l2w[q]; WM[q] = muw[q]; WV[q] = lvw[q];
    }
    if (tid < 12) { B1[tid] = l1b[tid]; B2[tid] = l2b[tid]; BM[tid] = mub[tid]; BV[tid] = lvb[tid]; }
    __syncthreads();

    int row = blockIdx.x * blockDim.x + tid;
    if (row >= BATCH * NLAY) return;
    const float* hp = g_hid + (size_t)row * HID;
    float h[HID], v1[HID], v2[HID];
    {
        float4 a = *(const float4*)(hp);
        float4 bq = *(const float4*)(hp + 4);
        float4 cq = *(const float4*)(hp + 8);
        h[0]=a.x; h[1]=a.y; h[2]=a.z; h[3]=a.w; h[4]=bq.x; h[5]=bq.y; h[6]=bq.z; h[7]=bq.w;
        h[8]=cq.x; h[9]=cq.y; h[10]=cq.z; h[11]=cq.w;
    }
    #pragma unroll
    for (int r = 0; r < HID; r++) {
        float a = B1[r];
        #pragma unroll
        for (int m = 0; m < HID; m++) a = fmaf(W1[r * HID + m], h[m], a);
        v1[r] = fmaxf(a, 0.f);
    }
    #pragma unroll
    for (int r = 0; r < HID; r++) {
        float a = B2[r];
        #pragma unroll
        for (int m = 0; m < HID; m++) a = fmaf(W2[r * HID + m], v1[m], a);
        v2[r] = fmaxf(a, 0.f);
    }
    #pragma unroll
    for (int r = 0; r < HID; r++) {
        float mu = BM[r], lv = BV[r];
        #pragma unroll
        for (int m = 0; m < HID; m++) {
            mu = fmaf(WM[r * HID + m], v2[m], mu);
            lv = fmaf(WV[r * HID + m], v2[m], lv);
        }
        float e = eps[(size_t)row * HID + r];
        float z = fmaf(__expf(0.5f * lv), e, mu);
        size_t idx = (size_t)row * HID + r;
        out[idx]                    = z;
        out[NOUT + idx]             = v2[r];
        out[2 * (size_t)NOUT + idx] = mu;
        out[3 * (size_t)NOUT + idx] = lv;
    }
}

// ---------------- launcher ----------------
extern "C" void kernel_launch(void* const* d_in, const int* in_sizes, int n_in,
                              void* d_out, int out_size) {
    const float* x    = (const float*)d_in[0];
    const float* eps  = (const float*)d_in[1];
    const float* c1w  = (const float*)d_in[2];
    const float* c1b  = (const float*)d_in[3];
    const float* c2w  = (const float*)d_in[4];
    const float* c2b  = (const float*)d_in[5];
    const float* bn1g = (const float*)d_in[6];
    const float* bn1b = (const float*)d_in[7];
    const float* bn2g = (const float*)d_in[8];
    const float* bn2b = (const float*)d_in[9];
    const float* aw   = (const float*)d_in[10];
    const float* ab   = (const float*)d_in[11];
    const float* Wih  = (const float*)d_in[12];
    const float* Whh  = (const float*)d_in[13];
    const float* bih  = (const float*)d_in[14];
    const float* bhh  = (const float*)d_in[15];
    const float* l1w  = (const float*)d_in[16];
    const float* l1b  = (const float*)d_in[17];
    const float* l2w  = (const float*)d_in[18];
    const float* l2b  = (const float*)d_in[19];
    const float* muw  = (const float*)d_in[20];
    const float* mub  = (const float*)d_in[21];
    const float* lvw  = (const float*)d_in[22];
    const float* lvb  = (const float*)d_in[23];

    cudaFuncSetAttribute(k_lstm3, cudaFuncAttributeMaxDynamicSharedMemorySize,
                         LSTM3_SMEM);

    k_zero<<<1, 256>>>();
    k_conv1<<<BATCH, 256>>>(x, c1w, c1b);
    k_bnfin<<<1, 32>>>(bn1g, bn1b, 0);
    k_conv2<<<BATCH, 256>>>(c2w, c2b);
    k_bnfin<<<1, 32>>>(bn2g, bn2b, 1);
    k_attn<<<BATCH, 256>>>(aw, ab);
    k_lstm3<<<NLAY, NTH3, LSTM3_SMEM>>>(Wih, Whh, bih, bhh);
    k_head<<<(BATCH * NLAY) / 128, 128>>>(eps, l1w, l1b, l2w, l2b, muw, mub, lvw, lvb,
                                          (float*)d_out);
}